// round 11
// baseline (speedup 1.0000x reference)
#include <cuda_runtime.h>
#include <cuda_bf16.h>
#include <cstdint>

// RocketConv: 84 ternary dilated depthwise kernels (alpha=-1, beta=2 at 3 taps).
// y_k[t] = -S(t) + 3*(s_a + s_b + s_c),  s_j = x[t + 4j - 16],  S = sum_j s_j
// Output layout (reference's double reshape) is flat (B, C, K, T):
//   out[((b*16 + c)*84 + k)*4096 + t]
//
// R10: discriminate "HBM write wall" vs "SM store-path wall".
// Compute the whole (84 k) x (256 t) tile into SMEM, then deliver it with
// cp.async.bulk (global <- shared::cta) 1 KB bursts: bypasses L1 entirely,
// full-line writes into L2, frees the SM store path. If the prior 53.7us
// plateau was SM-side, this drops to ~48-50us; if it's the HBM write
// ceiling, it stays flat and R5 (__stcs) is the wall.

#define T_LEN    4096
#define SEG      256
#define NTHREADS 256
#define HALO     16
#define TILE_F   320                       // 288 used, padded to keep 16B align
#define OUT_F    (84 * SEG)                // 21504 floats = 84 KB
#define SMEM_BYTES ((TILE_F + OUT_F) * 4)  // 87296 B

__global__ void rocketconv_kernel(const float* __restrict__ x,
                                  float* __restrict__ out) {
    extern __shared__ __align__(16) float smem[];
    float* __restrict__ tile = smem;            // input segment + halo
    float* __restrict__ outs = smem + TILE_F;   // [k][t] tile, 1 KB per k row

    const int tid = threadIdx.x;
    const int row = blockIdx.y;                 // b*16 + c
    const int seg = blockIdx.x * SEG;           // start t of this segment
    const float* __restrict__ xrow = x + (size_t)row * T_LEN;

    // Stage the row segment (+/-16 halo, zero padded).
    for (int i = tid; i < SEG + 2 * HALO; i += NTHREADS) {
        const int g = seg - HALO + i;
        tile[i] = (g >= 0 && g < T_LEN) ? xrow[g] : 0.0f;
    }
    __syncthreads();

    // Thread owns t = seg + tid. Tap j = tile[tid + 4*j] (t + 4j - 16).
    float t9[9];
    #pragma unroll
    for (int j = 0; j < 9; j++) t9[j] = tile[tid + 4 * j];

    float S = 0.f;
    #pragma unroll
    for (int j = 0; j < 9; j++) S += t9[j];
    const float nS = -S;

    int k = 0;
    #pragma unroll
    for (int a = 0; a < 9; a++) {
        #pragma unroll
        for (int b = a + 1; b < 9; b++) {
            const float p = t9[a] + t9[b];
            #pragma unroll
            for (int c = b + 1; c < 9; c++) {
                outs[k * SEG + tid] = fmaf(3.0f, p + t9[c], nS);
                k++;
            }
        }
    }
    __syncthreads();

    // Order generic STS writes before the async proxy, then fire 84 x 1KB
    // bulk copies (one per thread tid<84): SMEM -> L2 -> DRAM, no L1.
    asm volatile("fence.proxy.async.shared::cta;" ::: "memory");

    if (tid < 84) {
        float* gdst = out + ((size_t)row * 84 + tid) * T_LEN + seg;
        uint32_t ssrc = (uint32_t)__cvta_generic_to_shared(outs + tid * SEG);
        asm volatile(
            "cp.async.bulk.global.shared::cta.bulk_group [%0], [%1], %2;"
            :: "l"(gdst), "r"(ssrc), "r"(SEG * 4) : "memory");
        asm volatile("cp.async.bulk.commit_group;" ::: "memory");
        // Wait only for SMEM reads (smem freed at block exit); gmem writes
        // complete by kernel end per bulk-async semantics.
        asm volatile("cp.async.bulk.wait_group.read 0;" ::: "memory");
    }
}

extern "C" void kernel_launch(void* const* d_in, const int* in_sizes, int n_in,
                              void* d_out, int out_size) {
    const float* x = (const float*)d_in[0];
    float* out = (float*)d_out;
    cudaFuncSetAttribute(rocketconv_kernel,
                         cudaFuncAttributeMaxDynamicSharedMemorySize,
                         SMEM_BYTES);
    dim3 grid(T_LEN / SEG, 16 * 16);   // (16, 256)
    rocketconv_kernel<<<grid, NTHREADS, SMEM_BYTES>>>(x, out);
}

// round 12
// speedup vs baseline: 1.4874x; 1.4874x over previous
#include <cuda_runtime.h>
#include <cuda_bf16.h>
#include <cstdint>

// RocketConv: 84 ternary dilated depthwise kernels (alpha=-1, beta=2 at 3 taps).
// y_k[t] = -S(t) + 3*(s_a + s_b + s_c),  s_j = x[t + 4j - 16],  S = sum_j s_j
// Output flat layout (B, C, K, T): out[((b*16+c)*84 + k)*4096 + t]
//
// R11: clean rerun of the R10 bulk-store experiment. R10 was confounded by
// 87 KB smem -> occ 17% -> only ~300 in-flight 1KB copies. Split k-range in
// half per block (template KBASE): smem 44 KB -> 5 blocks/SM (62% occ),
// ~8x the in-flight TMA copies. Decides HBM-write-wall vs SM-store-path.

#define T_LEN    4096
#define SEG      256
#define NTHREADS 256
#define HALO     16
#define TILE_F   320                       // 288 used, padded
#define K_HALF   42
#define OUT_F    (K_HALF * SEG)            // 10752 floats = 43 KB
#define SMEM_BYTES ((TILE_F + OUT_F) * 4)  // 44288 B

template <int KBASE>
__global__ void rocketconv_kernel(const float* __restrict__ x,
                                  float* __restrict__ out) {
    extern __shared__ __align__(16) float smem[];
    float* __restrict__ tile = smem;            // input segment + halo
    float* __restrict__ outs = smem + TILE_F;   // [42][256] tile, 1 KB per k

    const int tid = threadIdx.x;
    const int row = blockIdx.y;                 // b*16 + c
    const int seg = blockIdx.x * SEG;
    const float* __restrict__ xrow = x + (size_t)row * T_LEN;

    for (int i = tid; i < SEG + 2 * HALO; i += NTHREADS) {
        const int g = seg - HALO + i;
        tile[i] = (g >= 0 && g < T_LEN) ? xrow[g] : 0.0f;
    }
    __syncthreads();

    // Thread owns t = seg + tid. Tap j = tile[tid + 4*j] (t + 4j - 16).
    float t9[9];
    #pragma unroll
    for (int j = 0; j < 9; j++) t9[j] = tile[tid + 4 * j];

    float S = 0.f;
    #pragma unroll
    for (int j = 0; j < 9; j++) S += t9[j];
    const float nS = -S;

    // Enumerate all 84 combos in lex order; keep only [KBASE, KBASE+42).
    // KBASE is a template constant -> dead halves eliminated at compile time.
    int k = 0;
    #pragma unroll
    for (int a = 0; a < 9; a++) {
        #pragma unroll
        for (int b = a + 1; b < 9; b++) {
            const float p = t9[a] + t9[b];
            #pragma unroll
            for (int c = b + 1; c < 9; c++) {
                if (k >= KBASE && k < KBASE + K_HALF)
                    outs[(k - KBASE) * SEG + tid] = fmaf(3.0f, p + t9[c], nS);
                k++;
            }
        }
    }
    __syncthreads();

    // Order STS before the async proxy, then 42 x 1KB bulk copies
    // (SMEM -> L2 -> DRAM, bypassing L1 / the STG wavefront path).
    asm volatile("fence.proxy.async.shared::cta;" ::: "memory");

    if (tid < K_HALF) {
        float* gdst = out + ((size_t)row * 84 + KBASE + tid) * T_LEN + seg;
        uint32_t ssrc = (uint32_t)__cvta_generic_to_shared(outs + tid * SEG);
        asm volatile(
            "cp.async.bulk.global.shared::cta.bulk_group [%0], [%1], %2;"
            :: "l"(gdst), "r"(ssrc), "r"(SEG * 4) : "memory");
        asm volatile("cp.async.bulk.commit_group;" ::: "memory");
        // Wait for SMEM reads only; gmem writes complete by kernel end.
        asm volatile("cp.async.bulk.wait_group.read 0;" ::: "memory");
    }
}

extern "C" void kernel_launch(void* const* d_in, const int* in_sizes, int n_in,
                              void* d_out, int out_size) {
    const float* x = (const float*)d_in[0];
    float* out = (float*)d_out;
    cudaFuncSetAttribute(rocketconv_kernel<0>,
                         cudaFuncAttributeMaxDynamicSharedMemorySize, SMEM_BYTES);
    cudaFuncSetAttribute(rocketconv_kernel<K_HALF>,
                         cudaFuncAttributeMaxDynamicSharedMemorySize, SMEM_BYTES);
    dim3 grid(T_LEN / SEG, 16 * 16);   // (16, 256) x 2 launches
    rocketconv_kernel<0>     <<<grid, NTHREADS, SMEM_BYTES>>>(x, out);
    rocketconv_kernel<K_HALF><<<grid, NTHREADS, SMEM_BYTES>>>(x, out);
}

// round 13
// speedup vs baseline: 1.7334x; 1.1654x over previous
#include <cuda_runtime.h>
#include <cuda_bf16.h>

// RocketConv: 84 ternary dilated depthwise kernels (alpha=-1, beta=2 at 3 taps).
// y_k[t] = -S(t) + 3*(s_a + s_b + s_c),  s_j = x[t + 4j - 16],  S = sum_j s_j
// Output layout (reference's double reshape) is flat (B, C, K, T):
//   out[((b*16 + c)*84 + k)*4096 + t]
//
// FINAL (R12): certified memory-wall kernel. Six structural designs tested
// (store width/occupancy sweeps, .wb, partial L2 residency, cp.async.bulk);
// all alternatives were flat or regressions. Wall-effective write rate is
// pinned at 352 MB / 53.7 us = 6.55 TB/s ~= 82% of HBM3e spec = the
// pure-write-stream ceiling. This is the fastest measured configuration:
// __stcs streaming stores, 128 thr/block, SEG=256, 4096 fine-grain blocks.

#define T_LEN    4096
#define SEG      256
#define NTHREADS 128
#define HALO     16
#define TILE_F   (SEG + 2 * HALO)   // 288 floats = 1.15 KB

__global__ __launch_bounds__(NTHREADS, 12)
void rocketconv_kernel(const float* __restrict__ x, float* __restrict__ out) {
    const int row = blockIdx.y;                 // b*16 + c
    const int seg = blockIdx.x * SEG;           // start t of this segment
    const float* __restrict__ xrow = x + (size_t)row * T_LEN;

    // Stage the row segment (+/-16 halo, zero padded) into shared memory.
    __shared__ __align__(16) float tile[TILE_F];
    for (int i = threadIdx.x; i < TILE_F; i += NTHREADS) {
        const int g = seg - HALO + i;
        tile[i] = (g >= 0 && g < T_LEN) ? xrow[g] : 0.0f;
    }
    __syncthreads();

    // Thread handles t0, t0+1 with t0 = seg + 2*tid.
    // Tap j for (t0+dt) is tile[2*tid + 4*j + dt] -> aligned float2 per tap.
    const float2* __restrict__ tp =
        reinterpret_cast<const float2*>(tile + 2 * threadIdx.x);   // tap j = tp[2*j]

    float2 t9[9];
    #pragma unroll
    for (int j = 0; j < 9; j++) t9[j] = tp[2 * j];

    float Sx = 0.f, Sy = 0.f;
    #pragma unroll
    for (int j = 0; j < 9; j++) { Sx += t9[j].x; Sy += t9[j].y; }
    const float nSx = -Sx, nSy = -Sy;

    // Output base for k=0 at this thread's t0; k-stride = 4096 floats = 2048 float2.
    float2* __restrict__ obase = reinterpret_cast<float2*>(
        out + (size_t)row * 84 * T_LEN + seg) + threadIdx.x;

    // Triangular combo enumeration in lex order; pair-sum reuse amortizes the
    // 84 outputs to ~1 ADD + 1 FMA per element per lane.
    int k = 0;
    #pragma unroll
    for (int a = 0; a < 9; a++) {
        #pragma unroll
        for (int b = a + 1; b < 9; b++) {
            const float px = t9[a].x + t9[b].x;
            const float py = t9[a].y + t9[b].y;
            #pragma unroll
            for (int c = b + 1; c < 9; c++) {
                float2 r;
                r.x = fmaf(3.0f, px + t9[c].x, nSx);
                r.y = fmaf(3.0f, py + t9[c].y, nSy);
                // Streaming store: write-once 352 MB output, evict-first in L2.
                __stcs(obase + (size_t)k * (T_LEN / 2), r);
                k++;
            }
        }
    }
}

extern "C" void kernel_launch(void* const* d_in, const int* in_sizes, int n_in,
                              void* d_out, int out_size) {
    const float* x = (const float*)d_in[0];
    float* out = (float*)d_out;
    dim3 grid(T_LEN / SEG, 16 * 16);   // (16, 256)
    rocketconv_kernel<<<grid, NTHREADS>>>(x, out);
}